// round 15
// baseline (speedup 1.0000x reference)
#include <cuda_runtime.h>
#include <math.h>

// ---------------------------------------------------------------------------
// NeuralSDE (Euler-Heun / Stratonovich) persistent kernel, round 14.
// Base = round-13 (16.54ms best). Change: diffusion inner loop reduced from
// 8 to 7 issue slots/k by pre-splatting h1c activations in smem (producers
// write (x_s,x_s) u64 pairs); the loaded weight pair feeds fma2 directly,
// eliminating both per-k MOV splats. Accumulation order per (col,sample) is
// bitwise unchanged.
// ---------------------------------------------------------------------------

#define kH     64
#define kNoise 16
#define kData  8
#define kW     128
#define kB     512
#define kT     1025
#define kSteps 1024
#define BS     4
#define NCTA   128
#define NTHR   512
#define kCO    1024

using u64 = unsigned long long;

// Transposed big weights (k-major). 8B-aligned for packed loads.
__device__ u64   g_cW2t[kW * kCO / 2];   // float (k,j) at k*1024 + j
__device__ float g_vW2t[kW * kH];        // float (k,h) at k*64 + h

struct Smem {
  float vW0t[65][kW];
  float cW0t[65][kW];
  float vW1t[kW][kW];
  float cW1t[kW][kW];
  float vb0[kW], vb1[kW], cb0[kW], cb1[kW];
  float vb2[kH], vscl[kH];
  float cb2[kCO];
  float cscl[kCO];
  float roWt[kH][kData];
  float rob[kData];
  // activations: float4 over the 4 samples
  float4 ys4[kH];
  float4 g04[kH];
  float4 f04[kH];
  float4 yp4[kH];
  float4 h0v4[kW];
  float4 h0c4[kW];
  float4 h1v4[kW];
  u64    h1csp[kW][4];   // c-net h1, SPLATTED per sample: [k][s] = (x_s, x_s)
  float  dws[BS][kNoise];
};

__global__ void transpose_kernel(const float* __restrict__ cW2,
                                 const float* __restrict__ vW2) {
  int idx = blockIdx.x * blockDim.x + threadIdx.x;
  int stride = gridDim.x * blockDim.x;
  float* ct = reinterpret_cast<float*>(g_cW2t);
  for (int i = idx; i < kW * kCO; i += stride) {
    int k = i >> 10, j = i & (kCO - 1);
    ct[i] = cW2[j * kW + k];            // cW2 is (1024, 128) row-major
  }
  for (int i = idx; i < kW * kH; i += stride) {
    int k = i >> 6, h = i & (kH - 1);
    g_vW2t[i] = vW2[h * kW + k];        // vW2 is (64, 128) row-major
  }
}

__device__ __forceinline__ u64 pack2(float lo, float hi) {
  u64 r; asm("mov.b64 %0,{%1,%2};" : "=l"(r) : "f"(lo), "f"(hi)); return r;
}
__device__ __forceinline__ void unpack2(u64 v, float& lo, float& hi) {
  asm("mov.b64 {%0,%1},%2;" : "=f"(lo), "=f"(hi) : "l"(v));
}
__device__ __forceinline__ u64 fma2(u64 a, u64 b, u64 c) {
  u64 d; asm("fma.rn.f32x2 %0,%1,%2,%3;" : "=l"(d) : "l"(a), "l"(b), "l"(c));
  return d;
}
__device__ __forceinline__ u64 add2(u64 a, u64 b) {
  u64 d; asm("add.rn.f32x2 %0,%1,%2;" : "=l"(d) : "l"(a), "l"(b));
  return d;
}

// Hardware tanh approximation (MUFU.TANH), max rel err ~2^-11.
__device__ __forceinline__ float tanh_fast(float x) {
  float y; asm("tanh.approx.f32 %0,%1;" : "=f"(y) : "f"(x));
  return y;
}

// lipswish(x) = 0.909 * x * sigmoid(x), sigmoid via 0.5 + 0.5*tanh(x/2).
__device__ __forceinline__ float lipswish(float x) {
  float t = tanh_fast(0.5f * x);
  return 0.909f * x * fmaf(0.5f, t, 0.5f);
}

// One (net,j) output for all 4 samples (used in phases A/B; 256 threads).
__device__ __forceinline__ float4 dense4(const float (*Wt)[kW], int j,
                                         const float4* __restrict__ x4,
                                         int k0, int n, float bias0) {
  u64 a01 = pack2(bias0, bias0), a23 = a01;
  u64 b01 = pack2(0.f, 0.f), b23 = b01;
#pragma unroll 4
  for (int k = k0; k < k0 + n; k += 2) {
    float wa = Wt[k][j];
    ulonglong2 xa = *reinterpret_cast<const ulonglong2*>(&x4[k - k0]);
    u64 wa2 = pack2(wa, wa);
    a01 = fma2(wa2, xa.x, a01);
    a23 = fma2(wa2, xa.y, a23);
    float wb = Wt[k + 1][j];
    ulonglong2 xb = *reinterpret_cast<const ulonglong2*>(&x4[k + 1 - k0]);
    u64 wb2 = pack2(wb, wb);
    b01 = fma2(wb2, xb.x, b01);
    b23 = fma2(wb2, xb.y, b23);
  }
  a01 = add2(a01, b01);
  a23 = add2(a23, b23);
  float4 r;
  unpack2(a01, r.x, r.y);
  unpack2(a23, r.z, r.w);
  return r;
}

// One (net,j) output for 2 samples (pr half); used in phases D/E (256 thr).
__device__ __forceinline__ float2 dense2(const float (*Wt)[kW], int j, int pr,
                                         const float4* __restrict__ x4,
                                         int n, float bias0) {
  u64 a = pack2(bias0, bias0);
  u64 b = pack2(0.f, 0.f);
#pragma unroll 8
  for (int k = 0; k < n; k += 2) {
    float wa = Wt[k][j];
    u64 xa = *reinterpret_cast<const u64*>(
        reinterpret_cast<const float*>(&x4[k]) + 2 * pr);
    a = fma2(pack2(wa, wa), xa, a);
    float wb = Wt[k + 1][j];
    u64 xb = *reinterpret_cast<const u64*>(
        reinterpret_cast<const float*>(&x4[k + 1]) + 2 * pr);
    b = fma2(pack2(wb, wb), xb, b);
  }
  a = add2(a, b);
  float2 r;
  unpack2(a, r.x, r.y);
  return r;
}

__global__ __launch_bounds__(NTHR, 1) void sde_kernel(
    const float* __restrict__ ts, const float* __restrict__ z0,
    const float* __restrict__ dW,
    const float* __restrict__ iW0, const float* __restrict__ ib0,
    const float* __restrict__ iW1, const float* __restrict__ ib1,
    const float* __restrict__ iW2, const float* __restrict__ ib2,
    const float* __restrict__ vW0, const float* __restrict__ vb0,
    const float* __restrict__ vW1, const float* __restrict__ vb1,
    const float* __restrict__ vb2, const float* __restrict__ vscale,
    const float* __restrict__ cW0, const float* __restrict__ cb0,
    const float* __restrict__ cW1, const float* __restrict__ cb1,
    const float* __restrict__ cb2, const float* __restrict__ cscale,
    const float* __restrict__ roW, const float* __restrict__ rob,
    float* __restrict__ out) {
  extern __shared__ char smem_raw[];
  Smem& s = *reinterpret_cast<Smem*>(smem_raw);
  const int tid = threadIdx.x;
  const int bbase = blockIdx.x * BS;

  // ---- load small weights transposed into smem ----
  for (int i = tid; i < 65 * kW; i += NTHR) {
    int k = i >> 7, j = i & 127;
    s.vW0t[k][j] = vW0[j * 65 + k];
    s.cW0t[k][j] = cW0[j * 65 + k];
  }
  for (int i = tid; i < kW * kW; i += NTHR) {
    int k = i >> 7, j = i & 127;
    s.vW1t[k][j] = vW1[j * kW + k];
    s.cW1t[k][j] = cW1[j * kW + k];
  }
  for (int i = tid; i < kW; i += NTHR) {
    s.vb0[i] = vb0[i]; s.vb1[i] = vb1[i];
    s.cb0[i] = cb0[i]; s.cb1[i] = cb1[i];
  }
  for (int i = tid; i < kH; i += NTHR) { s.vb2[i] = vb2[i]; s.vscl[i] = vscale[i]; }
  for (int i = tid; i < kCO; i += NTHR) { s.cb2[i] = cb2[i]; s.cscl[i] = cscale[i]; }
  for (int i = tid; i < kH * kData; i += NTHR) {
    int h = i >> 3, d = i & 7;
    s.roWt[h][d] = roW[d * kH + h];
  }
  if (tid < kData) s.rob[tid] = rob[tid];
  __syncthreads();

  const float dt = __ldg(&ts[1]) - __ldg(&ts[0]);
  const float sqdt = sqrtf(dt);

  // ---- initial MLP: z0 (8) -> relu 128 -> relu 128 -> 64 ----
  if (tid < 256) {
    int j = tid & 127, pr = tid >> 7;  // samples 2pr, 2pr+1
    float a0 = __ldg(&ib0[j]), a1 = a0;
#pragma unroll
    for (int k = 0; k < 8; ++k) {
      float w = __ldg(&iW0[j * 8 + k]);
      a0 = fmaf(w, __ldg(&z0[(bbase + 2 * pr) * 8 + k]), a0);
      a1 = fmaf(w, __ldg(&z0[(bbase + 2 * pr + 1) * 8 + k]), a1);
    }
    float* d0 = reinterpret_cast<float*>(&s.h0v4[j]) + 2 * pr;
    d0[0] = fmaxf(a0, 0.f); d0[1] = fmaxf(a1, 0.f);
  }
  __syncthreads();
  if (tid < 256) {
    int j = tid & 127, pr = tid >> 7;
    float a0 = __ldg(&ib1[j]), a1 = a0;
#pragma unroll 4
    for (int k = 0; k < kW; ++k) {
      float w = __ldg(&iW1[j * kW + k]);
      const float* x = reinterpret_cast<const float*>(&s.h0v4[k]) + 2 * pr;
      a0 = fmaf(w, x[0], a0);
      a1 = fmaf(w, x[1], a1);
    }
    float* d0 = reinterpret_cast<float*>(&s.h0c4[j]) + 2 * pr;  // temp
    d0[0] = fmaxf(a0, 0.f); d0[1] = fmaxf(a1, 0.f);
  }
  __syncthreads();
  if (tid < 256) {
    int b = tid >> 6, h = tid & 63;
    float acc = __ldg(&ib2[h]);
#pragma unroll 4
    for (int k = 0; k < kW; ++k)
      acc = fmaf(reinterpret_cast<const float*>(&s.h0c4[k])[b],
                 __ldg(&iW2[h * kW + k]), acc);
    reinterpret_cast<float*>(&s.ys4[h])[b] = acc;
  }
  __syncthreads();

  // precomputed per-thread constants
  const int jA = tid & 127;             // phases A/B: (net, j), 4 samples
  const int netA = tid >> 7;            // valid for tid < 256
  const int prDE = tid >> 7;            // phases D/E sample pair (tid < 256)
  const int j0 = tid << 1;              // diffusion col pair (phases C/F)
  const int hC = tid >> 3;              // diffusion h
  const u64* wrowC = g_cW2t + tid;      // row k at + k*512 (u64 units)
  const int hDr = tid - 256;            // drift h (tid in [256,320))

  for (int st = 0; st < kSteps; ++st) {
    const float tcur = __ldg(&ts[st]);

    // ================= phase A: dense L0 of both nets + extras ===========
    if (tid < 256) {
      const float (*W0)[kW] = netA ? s.cW0t : s.vW0t;
      const float* bb = netA ? s.cb0 : s.vb0;
      float bi = fmaf(W0[0][jA], tcur, bb[jA]);
      float4 r = dense4(&W0[1], jA, s.ys4, 0, kH, bi);
      float4 h; h.x = lipswish(r.x); h.y = lipswish(r.y);
      h.z = lipswish(r.z); h.w = lipswish(r.w);
      (netA ? s.h0c4 : s.h0v4)[jA] = h;
    } else if (tid >= 448) {
      int i = tid - 448;                 // 64 tasks: dW load
      int b = i >> 4, n = i & 15;
      s.dws[b][n] = __ldg(&dW[((size_t)st * kB + bbase + b) * kNoise + n]) * sqdt;
    } else if (tid >= 416) {
      int i = tid - 416;                 // 32 tasks: readout of y_st
      int b = i >> 3, d = i & 7;
      float acc = s.rob[d];
#pragma unroll
      for (int h = 0; h < kH; ++h)
        acc = fmaf(reinterpret_cast<const float*>(&s.ys4[h])[b], s.roWt[h][d], acc);
      out[((size_t)(bbase + b) * kT + st) * kData + d] = acc;
    }
    __syncthreads();

    // ================= phase B: dense L1 of both nets ====================
    if (tid < 256) {
      const float (*W1)[kW] = netA ? s.cW1t : s.vW1t;
      const float* bb = netA ? s.cb1 : s.vb1;
      const float4* src = netA ? s.h0c4 : s.h0v4;
      float4 r = dense4(W1, jA, src, 0, kW, bb[jA]);
      float4 h; h.x = lipswish(r.x); h.y = lipswish(r.y);
      h.z = lipswish(r.z); h.w = lipswish(r.w);
      if (netA) {
        ulonglong2 lo, hi;
        lo.x = pack2(h.x, h.x); lo.y = pack2(h.y, h.y);
        hi.x = pack2(h.z, h.z); hi.y = pack2(h.w, h.w);
        *reinterpret_cast<ulonglong2*>(&s.h1csp[jA][0]) = lo;
        *reinterpret_cast<ulonglong2*>(&s.h1csp[jA][2]) = hi;
      } else {
        s.h1v4[jA] = h;
      }
    }
    __syncthreads();

    // ================= phase C: diffusion eval 1 (all threads) ===========
    {
      const float2 cb = *reinterpret_cast<const float2*>(&s.cb2[j0]);
      const u64 binit = pack2(cb.x, cb.y);        // (col j0, col j0+1)
      u64 A0 = binit, A1 = binit, A2 = binit, A3 = binit;   // per sample
#pragma unroll 8
      for (int k = 0; k < kW; ++k) {
        u64 w2 = wrowC[(size_t)k * (kCO / 2)];    // (w_j0, w_j1)
        ulonglong2 xa = *reinterpret_cast<const ulonglong2*>(&s.h1csp[k][0]);
        ulonglong2 xb = *reinterpret_cast<const ulonglong2*>(&s.h1csp[k][2]);
        A0 = fma2(w2, xa.x, A0);
        A1 = fma2(w2, xa.y, A1);
        A2 = fma2(w2, xb.x, A2);
        A3 = fma2(w2, xb.y, A3);
      }
      float csx = s.cscl[j0], csy = s.cscl[j0 + 1];
      int n0 = j0 & (kNoise - 1);
      float2 d0 = *reinterpret_cast<const float2*>(&s.dws[0][n0]);
      float2 d1 = *reinterpret_cast<const float2*>(&s.dws[1][n0]);
      float2 d2 = *reinterpret_cast<const float2*>(&s.dws[2][n0]);
      float2 d3 = *reinterpret_cast<const float2*>(&s.dws[3][n0]);
      float s0j0, s0j1, s1j0, s1j1, s2j0, s2j1, s3j0, s3j1;
      unpack2(A0, s0j0, s0j1); unpack2(A1, s1j0, s1j1);
      unpack2(A2, s2j0, s2j1); unpack2(A3, s3j0, s3j1);
      float p0 = tanh_fast(s0j0) * csx * d0.x + tanh_fast(s0j1) * csy * d0.y;
      float p1 = tanh_fast(s1j0) * csx * d1.x + tanh_fast(s1j1) * csy * d1.y;
      float p2 = tanh_fast(s2j0) * csx * d2.x + tanh_fast(s2j1) * csy * d2.y;
      float p3 = tanh_fast(s3j0) * csx * d3.x + tanh_fast(s3j1) * csy * d3.y;
      p0 += __shfl_xor_sync(~0u, p0, 1); p0 += __shfl_xor_sync(~0u, p0, 2); p0 += __shfl_xor_sync(~0u, p0, 4);
      p1 += __shfl_xor_sync(~0u, p1, 1); p1 += __shfl_xor_sync(~0u, p1, 2); p1 += __shfl_xor_sync(~0u, p1, 4);
      p2 += __shfl_xor_sync(~0u, p2, 1); p2 += __shfl_xor_sync(~0u, p2, 2); p2 += __shfl_xor_sync(~0u, p2, 4);
      p3 += __shfl_xor_sync(~0u, p3, 1); p3 += __shfl_xor_sync(~0u, p3, 2); p3 += __shfl_xor_sync(~0u, p3, 4);
      if ((tid & 7) == 0) {
        float4 y = s.ys4[hC];
        float4 g; g.x = p0; g.y = p1; g.z = p2; g.w = p3;
        s.g04[hC] = g;
        float4 yp; yp.x = y.x + p0; yp.y = y.y + p1; yp.z = y.z + p2; yp.w = y.w + p3;
        s.yp4[hC] = yp;
      }
    }
    __syncthreads();

    // ================= phase D: c-net L0 at y' + drift final =============
    if (tid < 256) {
      float bi = fmaf(s.cW0t[0][jA], tcur, s.cb0[jA]);
      float2 r = dense2(&s.cW0t[1], jA, prDE, s.yp4, kH, bi);
      float2 h; h.x = lipswish(r.x); h.y = lipswish(r.y);
      *reinterpret_cast<float2*>(
          reinterpret_cast<float*>(&s.h0c4[jA]) + 2 * prDE) = h;
    } else if (tid < 320) {
      // drift final layer: one h for all 4 samples, streamed vW2t from L2
      float bias = s.vb2[hDr];
      u64 a01 = pack2(bias, bias), a23 = a01;
      u64 b01 = pack2(0.f, 0.f), b23 = b01;
#pragma unroll 8
      for (int k = 0; k < kW; k += 2) {
        float wa = __ldg(&g_vW2t[k * kH + hDr]);
        ulonglong2 xa = *reinterpret_cast<const ulonglong2*>(&s.h1v4[k]);
        u64 wa2 = pack2(wa, wa);
        a01 = fma2(wa2, xa.x, a01);
        a23 = fma2(wa2, xa.y, a23);
        float wb = __ldg(&g_vW2t[(k + 1) * kH + hDr]);
        ulonglong2 xb = *reinterpret_cast<const ulonglong2*>(&s.h1v4[k + 1]);
        u64 wb2 = pack2(wb, wb);
        b01 = fma2(wb2, xb.x, b01);
        b23 = fma2(wb2, xb.y, b23);
      }
      a01 = add2(a01, b01);
      a23 = add2(a23, b23);
      float r0, r1, r2, r3;
      unpack2(a01, r0, r1); unpack2(a23, r2, r3);
      float vs = s.vscl[hDr] * dt;
      float4 f; f.x = vs * tanh_fast(r0); f.y = vs * tanh_fast(r1);
      f.z = vs * tanh_fast(r2); f.w = vs * tanh_fast(r3);
      s.f04[hDr] = f;
    }
    __syncthreads();

    // ================= phase E: c-net L1 at y' ===========================
    if (tid < 256) {
      float2 r = dense2(s.cW1t, jA, prDE, s.h0c4, kW, s.cb1[jA]);
      float2 h; h.x = lipswish(r.x); h.y = lipswish(r.y);
      ulonglong2 sp;
      sp.x = pack2(h.x, h.x);
      sp.y = pack2(h.y, h.y);
      *reinterpret_cast<ulonglong2*>(&s.h1csp[jA][2 * prDE]) = sp;
    }
    __syncthreads();

    // ================= phase F: diffusion eval 2 + Heun update ===========
    {
      const float2 cb = *reinterpret_cast<const float2*>(&s.cb2[j0]);
      const u64 binit = pack2(cb.x, cb.y);
      u64 A0 = binit, A1 = binit, A2 = binit, A3 = binit;
#pragma unroll 8
      for (int k = 0; k < kW; ++k) {
        u64 w2 = wrowC[(size_t)k * (kCO / 2)];
        ulonglong2 xa = *reinterpret_cast<const ulonglong2*>(&s.h1csp[k][0]);
        ulonglong2 xb = *reinterpret_cast<const ulonglong2*>(&s.h1csp[k][2]);
        A0 = fma2(w2, xa.x, A0);
        A1 = fma2(w2, xa.y, A1);
        A2 = fma2(w2, xb.x, A2);
        A3 = fma2(w2, xb.y, A3);
      }
      float csx = s.cscl[j0], csy = s.cscl[j0 + 1];
      int n0 = j0 & (kNoise - 1);
      float2 d0 = *reinterpret_cast<const float2*>(&s.dws[0][n0]);
      float2 d1 = *reinterpret_cast<const float2*>(&s.dws[1][n0]);
      float2 d2 = *reinterpret_cast<const float2*>(&s.dws[2][n0]);
      float2 d3 = *reinterpret_cast<const float2*>(&s.dws[3][n0]);
      float s0j0, s0j1, s1j0, s1j1, s2j0, s2j1, s3j0, s3j1;
      unpack2(A0, s0j0, s0j1); unpack2(A1, s1j0, s1j1);
      unpack2(A2, s2j0, s2j1); unpack2(A3, s3j0, s3j1);
      float p0 = tanh_fast(s0j0) * csx * d0.x + tanh_fast(s0j1) * csy * d0.y;
      float p1 = tanh_fast(s1j0) * csx * d1.x + tanh_fast(s1j1) * csy * d1.y;
      float p2 = tanh_fast(s2j0) * csx * d2.x + tanh_fast(s2j1) * csy * d2.y;
      float p3 = tanh_fast(s3j0) * csx * d3.x + tanh_fast(s3j1) * csy * d3.y;
      p0 += __shfl_xor_sync(~0u, p0, 1); p0 += __shfl_xor_sync(~0u, p0, 2); p0 += __shfl_xor_sync(~0u, p0, 4);
      p1 += __shfl_xor_sync(~0u, p1, 1); p1 += __shfl_xor_sync(~0u, p1, 2); p1 += __shfl_xor_sync(~0u, p1, 4);
      p2 += __shfl_xor_sync(~0u, p2, 1); p2 += __shfl_xor_sync(~0u, p2, 2); p2 += __shfl_xor_sync(~0u, p2, 4);
      p3 += __shfl_xor_sync(~0u, p3, 1); p3 += __shfl_xor_sync(~0u, p3, 2); p3 += __shfl_xor_sync(~0u, p3, 4);
      if ((tid & 7) == 0) {
        float4 y = s.ys4[hC];
        float4 f = s.f04[hC];
        float4 g = s.g04[hC];
        y.x += f.x + 0.5f * (g.x + p0);
        y.y += f.y + 0.5f * (g.y + p1);
        y.z += f.z + 0.5f * (g.z + p2);
        y.w += f.w + 0.5f * (g.w + p3);
        s.ys4[hC] = y;
      }
    }
    __syncthreads();
  }

  // final readout (index kSteps)
  if (tid < 32) {
    int b = tid >> 3, d = tid & 7;
    float acc = s.rob[d];
#pragma unroll
    for (int h = 0; h < kH; ++h)
      acc = fmaf(reinterpret_cast<const float*>(&s.ys4[h])[b], s.roWt[h][d], acc);
    out[((size_t)(bbase + b) * kT + kSteps) * kData + d] = acc;
  }
}

extern "C" void kernel_launch(void* const* d_in, const int* in_sizes, int n_in,
                              void* d_out, int out_size) {
  (void)in_sizes; (void)n_in; (void)out_size;
  const float* ts     = (const float*)d_in[0];
  const float* z0     = (const float*)d_in[1];
  const float* dW     = (const float*)d_in[2];
  const float* iW0    = (const float*)d_in[3];
  const float* ib0    = (const float*)d_in[4];
  const float* iW1    = (const float*)d_in[5];
  const float* ib1    = (const float*)d_in[6];
  const float* iW2    = (const float*)d_in[7];
  const float* ib2    = (const float*)d_in[8];
  const float* vW0    = (const float*)d_in[9];
  const float* vb0    = (const float*)d_in[10];
  const float* vW1    = (const float*)d_in[11];
  const float* vb1    = (const float*)d_in[12];
  const float* vW2    = (const float*)d_in[13];
  const float* vb2    = (const float*)d_in[14];
  const float* vscale = (const float*)d_in[15];
  const float* cW0    = (const float*)d_in[16];
  const float* cb0    = (const float*)d_in[17];
  const float* cW1    = (const float*)d_in[18];
  const float* cb1    = (const float*)d_in[19];
  const float* cW2    = (const float*)d_in[20];
  const float* cb2    = (const float*)d_in[21];
  const float* cscale = (const float*)d_in[22];
  const float* roW    = (const float*)d_in[23];
  const float* rob    = (const float*)d_in[24];

  cudaFuncSetAttribute(sde_kernel, cudaFuncAttributeMaxDynamicSharedMemorySize,
                       (int)sizeof(Smem));

  transpose_kernel<<<148, 256>>>(cW2, vW2);
  sde_kernel<<<NCTA, NTHR, sizeof(Smem)>>>(
      ts, z0, dW, iW0, ib0, iW1, ib1, iW2, ib2,
      vW0, vb0, vW1, vb1, vb2, vscale,
      cW0, cb0, cW1, cb1, cb2, cscale, roW, rob,
      (float*)d_out);
}

// round 16
// speedup vs baseline: 1.2395x; 1.2395x over previous
#include <cuda_runtime.h>
#include <math.h>

// ---------------------------------------------------------------------------
// NeuralSDE (Euler-Heun / Stratonovich) persistent kernel, round 15.
// Base = round-13 (16.54ms best; R14's smem-splat regressed and is reverted).
// Scheduling-only change: diffusion C/F loops unroll 8 -> 16, dense4 unroll
// 4 -> 8. Instruction mix and arithmetic order unchanged (bitwise identical).
// ---------------------------------------------------------------------------

#define kH     64
#define kNoise 16
#define kData  8
#define kW     128
#define kB     512
#define kT     1025
#define kSteps 1024
#define BS     4
#define NCTA   128
#define NTHR   512
#define kCO    1024

using u64 = unsigned long long;

// Transposed big weights (k-major). 8B-aligned for packed loads.
__device__ u64   g_cW2t[kW * kCO / 2];   // float (k,j) at k*1024 + j
__device__ float g_vW2t[kW * kH];        // float (k,h) at k*64 + h

struct Smem {
  float vW0t[65][kW];
  float cW0t[65][kW];
  float vW1t[kW][kW];
  float cW1t[kW][kW];
  float vb0[kW], vb1[kW], cb0[kW], cb1[kW];
  float vb2[kH], vscl[kH];
  float cb2[kCO];
  float cscl[kCO];
  float roWt[kH][kData];
  float rob[kData];
  // activations: float4 over the 4 samples
  float4 ys4[kH];
  float4 g04[kH];
  float4 f04[kH];
  float4 yp4[kH];
  float4 h0v4[kW];
  float4 h0c4[kW];
  float4 h1v4[kW];
  float4 h1c4[kW];
  float  dws[BS][kNoise];
};

__global__ void transpose_kernel(const float* __restrict__ cW2,
                                 const float* __restrict__ vW2) {
  int idx = blockIdx.x * blockDim.x + threadIdx.x;
  int stride = gridDim.x * blockDim.x;
  float* ct = reinterpret_cast<float*>(g_cW2t);
  for (int i = idx; i < kW * kCO; i += stride) {
    int k = i >> 10, j = i & (kCO - 1);
    ct[i] = cW2[j * kW + k];            // cW2 is (1024, 128) row-major
  }
  for (int i = idx; i < kW * kH; i += stride) {
    int k = i >> 6, h = i & (kH - 1);
    g_vW2t[i] = vW2[h * kW + k];        // vW2 is (64, 128) row-major
  }
}

__device__ __forceinline__ u64 pack2(float lo, float hi) {
  u64 r; asm("mov.b64 %0,{%1,%2};" : "=l"(r) : "f"(lo), "f"(hi)); return r;
}
__device__ __forceinline__ void unpack2(u64 v, float& lo, float& hi) {
  asm("mov.b64 {%0,%1},%2;" : "=f"(lo), "=f"(hi) : "l"(v));
}
__device__ __forceinline__ u64 fma2(u64 a, u64 b, u64 c) {
  u64 d; asm("fma.rn.f32x2 %0,%1,%2,%3;" : "=l"(d) : "l"(a), "l"(b), "l"(c));
  return d;
}
__device__ __forceinline__ u64 add2(u64 a, u64 b) {
  u64 d; asm("add.rn.f32x2 %0,%1,%2;" : "=l"(d) : "l"(a), "l"(b));
  return d;
}

// Hardware tanh approximation (MUFU.TANH), max rel err ~2^-11.
__device__ __forceinline__ float tanh_fast(float x) {
  float y; asm("tanh.approx.f32 %0,%1;" : "=f"(y) : "f"(x));
  return y;
}

// lipswish(x) = 0.909 * x * sigmoid(x), sigmoid via 0.5 + 0.5*tanh(x/2).
__device__ __forceinline__ float lipswish(float x) {
  float t = tanh_fast(0.5f * x);
  return 0.909f * x * fmaf(0.5f, t, 0.5f);
}

// One (net,j) output for all 4 samples (used in phases A/B; 256 threads).
__device__ __forceinline__ float4 dense4(const float (*Wt)[kW], int j,
                                         const float4* __restrict__ x4,
                                         int k0, int n, float bias0) {
  u64 a01 = pack2(bias0, bias0), a23 = a01;
  u64 b01 = pack2(0.f, 0.f), b23 = b01;
#pragma unroll 8
  for (int k = k0; k < k0 + n; k += 2) {
    float wa = Wt[k][j];
    ulonglong2 xa = *reinterpret_cast<const ulonglong2*>(&x4[k - k0]);
    u64 wa2 = pack2(wa, wa);
    a01 = fma2(wa2, xa.x, a01);
    a23 = fma2(wa2, xa.y, a23);
    float wb = Wt[k + 1][j];
    ulonglong2 xb = *reinterpret_cast<const ulonglong2*>(&x4[k + 1 - k0]);
    u64 wb2 = pack2(wb, wb);
    b01 = fma2(wb2, xb.x, b01);
    b23 = fma2(wb2, xb.y, b23);
  }
  a01 = add2(a01, b01);
  a23 = add2(a23, b23);
  float4 r;
  unpack2(a01, r.x, r.y);
  unpack2(a23, r.z, r.w);
  return r;
}

// One (net,j) output for 2 samples (pr half); used in phases D/E (256 thr).
__device__ __forceinline__ float2 dense2(const float (*Wt)[kW], int j, int pr,
                                         const float4* __restrict__ x4,
                                         int n, float bias0) {
  u64 a = pack2(bias0, bias0);
  u64 b = pack2(0.f, 0.f);
#pragma unroll 8
  for (int k = 0; k < n; k += 2) {
    float wa = Wt[k][j];
    u64 xa = *reinterpret_cast<const u64*>(
        reinterpret_cast<const float*>(&x4[k]) + 2 * pr);
    a = fma2(pack2(wa, wa), xa, a);
    float wb = Wt[k + 1][j];
    u64 xb = *reinterpret_cast<const u64*>(
        reinterpret_cast<const float*>(&x4[k + 1]) + 2 * pr);
    b = fma2(pack2(wb, wb), xb, b);
  }
  a = add2(a, b);
  float2 r;
  unpack2(a, r.x, r.y);
  return r;
}

__global__ __launch_bounds__(NTHR, 1) void sde_kernel(
    const float* __restrict__ ts, const float* __restrict__ z0,
    const float* __restrict__ dW,
    const float* __restrict__ iW0, const float* __restrict__ ib0,
    const float* __restrict__ iW1, const float* __restrict__ ib1,
    const float* __restrict__ iW2, const float* __restrict__ ib2,
    const float* __restrict__ vW0, const float* __restrict__ vb0,
    const float* __restrict__ vW1, const float* __restrict__ vb1,
    const float* __restrict__ vb2, const float* __restrict__ vscale,
    const float* __restrict__ cW0, const float* __restrict__ cb0,
    const float* __restrict__ cW1, const float* __restrict__ cb1,
    const float* __restrict__ cb2, const float* __restrict__ cscale,
    const float* __restrict__ roW, const float* __restrict__ rob,
    float* __restrict__ out) {
  extern __shared__ char smem_raw[];
  Smem& s = *reinterpret_cast<Smem*>(smem_raw);
  const int tid = threadIdx.x;
  const int bbase = blockIdx.x * BS;

  // ---- load small weights transposed into smem ----
  for (int i = tid; i < 65 * kW; i += NTHR) {
    int k = i >> 7, j = i & 127;
    s.vW0t[k][j] = vW0[j * 65 + k];
    s.cW0t[k][j] = cW0[j * 65 + k];
  }
  for (int i = tid; i < kW * kW; i += NTHR) {
    int k = i >> 7, j = i & 127;
    s.vW1t[k][j] = vW1[j * kW + k];
    s.cW1t[k][j] = cW1[j * kW + k];
  }
  for (int i = tid; i < kW; i += NTHR) {
    s.vb0[i] = vb0[i]; s.vb1[i] = vb1[i];
    s.cb0[i] = cb0[i]; s.cb1[i] = cb1[i];
  }
  for (int i = tid; i < kH; i += NTHR) { s.vb2[i] = vb2[i]; s.vscl[i] = vscale[i]; }
  for (int i = tid; i < kCO; i += NTHR) { s.cb2[i] = cb2[i]; s.cscl[i] = cscale[i]; }
  for (int i = tid; i < kH * kData; i += NTHR) {
    int h = i >> 3, d = i & 7;
    s.roWt[h][d] = roW[d * kH + h];
  }
  if (tid < kData) s.rob[tid] = rob[tid];
  __syncthreads();

  const float dt = __ldg(&ts[1]) - __ldg(&ts[0]);
  const float sqdt = sqrtf(dt);

  // ---- initial MLP: z0 (8) -> relu 128 -> relu 128 -> 64 ----
  if (tid < 256) {
    int j = tid & 127, pr = tid >> 7;  // samples 2pr, 2pr+1
    float a0 = __ldg(&ib0[j]), a1 = a0;
#pragma unroll
    for (int k = 0; k < 8; ++k) {
      float w = __ldg(&iW0[j * 8 + k]);
      a0 = fmaf(w, __ldg(&z0[(bbase + 2 * pr) * 8 + k]), a0);
      a1 = fmaf(w, __ldg(&z0[(bbase + 2 * pr + 1) * 8 + k]), a1);
    }
    float* d0 = reinterpret_cast<float*>(&s.h0v4[j]) + 2 * pr;
    d0[0] = fmaxf(a0, 0.f); d0[1] = fmaxf(a1, 0.f);
  }
  __syncthreads();
  if (tid < 256) {
    int j = tid & 127, pr = tid >> 7;
    float a0 = __ldg(&ib1[j]), a1 = a0;
#pragma unroll 4
    for (int k = 0; k < kW; ++k) {
      float w = __ldg(&iW1[j * kW + k]);
      const float* x = reinterpret_cast<const float*>(&s.h0v4[k]) + 2 * pr;
      a0 = fmaf(w, x[0], a0);
      a1 = fmaf(w, x[1], a1);
    }
    float* d0 = reinterpret_cast<float*>(&s.h0c4[j]) + 2 * pr;  // temp
    d0[0] = fmaxf(a0, 0.f); d0[1] = fmaxf(a1, 0.f);
  }
  __syncthreads();
  if (tid < 256) {
    int b = tid >> 6, h = tid & 63;
    float acc = __ldg(&ib2[h]);
#pragma unroll 4
    for (int k = 0; k < kW; ++k)
      acc = fmaf(reinterpret_cast<const float*>(&s.h0c4[k])[b],
                 __ldg(&iW2[h * kW + k]), acc);
    reinterpret_cast<float*>(&s.ys4[h])[b] = acc;
  }
  __syncthreads();

  // precomputed per-thread constants
  const int jA = tid & 127;             // phases A/B: (net, j), 4 samples
  const int netA = tid >> 7;            // valid for tid < 256
  const int prDE = tid >> 7;            // phases D/E sample pair (tid < 256)
  const int j0 = tid << 1;              // diffusion col pair (phases C/F)
  const int hC = tid >> 3;              // diffusion h
  const u64* wrowC = g_cW2t + tid;      // row k at + k*512 (u64 units)
  const int hDr = tid - 256;            // drift h (tid in [256,320))

  for (int st = 0; st < kSteps; ++st) {
    const float tcur = __ldg(&ts[st]);

    // ================= phase A: dense L0 of both nets + extras ===========
    if (tid < 256) {
      const float (*W0)[kW] = netA ? s.cW0t : s.vW0t;
      const float* bb = netA ? s.cb0 : s.vb0;
      float bi = fmaf(W0[0][jA], tcur, bb[jA]);
      float4 r = dense4(&W0[1], jA, s.ys4, 0, kH, bi);
      float4 h; h.x = lipswish(r.x); h.y = lipswish(r.y);
      h.z = lipswish(r.z); h.w = lipswish(r.w);
      (netA ? s.h0c4 : s.h0v4)[jA] = h;
    } else if (tid >= 448) {
      int i = tid - 448;                 // 64 tasks: dW load
      int b = i >> 4, n = i & 15;
      s.dws[b][n] = __ldg(&dW[((size_t)st * kB + bbase + b) * kNoise + n]) * sqdt;
    } else if (tid >= 416) {
      int i = tid - 416;                 // 32 tasks: readout of y_st
      int b = i >> 3, d = i & 7;
      float acc = s.rob[d];
#pragma unroll
      for (int h = 0; h < kH; ++h)
        acc = fmaf(reinterpret_cast<const float*>(&s.ys4[h])[b], s.roWt[h][d], acc);
      out[((size_t)(bbase + b) * kT + st) * kData + d] = acc;
    }
    __syncthreads();

    // ================= phase B: dense L1 of both nets ====================
    if (tid < 256) {
      const float (*W1)[kW] = netA ? s.cW1t : s.vW1t;
      const float* bb = netA ? s.cb1 : s.vb1;
      const float4* src = netA ? s.h0c4 : s.h0v4;
      float4 r = dense4(W1, jA, src, 0, kW, bb[jA]);
      float4 h; h.x = lipswish(r.x); h.y = lipswish(r.y);
      h.z = lipswish(r.z); h.w = lipswish(r.w);
      (netA ? s.h1c4 : s.h1v4)[jA] = h;
    }
    __syncthreads();

    // ================= phase C: diffusion eval 1 (all threads) ===========
    {
      const float2 cb = *reinterpret_cast<const float2*>(&s.cb2[j0]);
      u64 A00 = pack2(cb.x, cb.x), A01 = A00;   // col j0: samples(0,1),(2,3)
      u64 A10 = pack2(cb.y, cb.y), A11 = A10;   // col j0+1
#pragma unroll 16
      for (int k = 0; k < kW; ++k) {
        u64 w2 = wrowC[(size_t)k * (kCO / 2)];
        float wlo, whi; unpack2(w2, wlo, whi);
        u64 w00 = pack2(wlo, wlo);
        u64 w11 = pack2(whi, whi);
        ulonglong2 x = *reinterpret_cast<const ulonglong2*>(&s.h1c4[k]);
        A00 = fma2(w00, x.x, A00);
        A01 = fma2(w00, x.y, A01);
        A10 = fma2(w11, x.x, A10);
        A11 = fma2(w11, x.y, A11);
      }
      float csx = s.cscl[j0], csy = s.cscl[j0 + 1];
      int n0 = j0 & (kNoise - 1);
      float2 d0 = *reinterpret_cast<const float2*>(&s.dws[0][n0]);
      float2 d1 = *reinterpret_cast<const float2*>(&s.dws[1][n0]);
      float2 d2 = *reinterpret_cast<const float2*>(&s.dws[2][n0]);
      float2 d3 = *reinterpret_cast<const float2*>(&s.dws[3][n0]);
      float s0j0, s1j0, s2j0, s3j0, s0j1, s1j1, s2j1, s3j1;
      unpack2(A00, s0j0, s1j0); unpack2(A01, s2j0, s3j0);
      unpack2(A10, s0j1, s1j1); unpack2(A11, s2j1, s3j1);
      float p0 = tanh_fast(s0j0) * csx * d0.x + tanh_fast(s0j1) * csy * d0.y;
      float p1 = tanh_fast(s1j0) * csx * d1.x + tanh_fast(s1j1) * csy * d1.y;
      float p2 = tanh_fast(s2j0) * csx * d2.x + tanh_fast(s2j1) * csy * d2.y;
      float p3 = tanh_fast(s3j0) * csx * d3.x + tanh_fast(s3j1) * csy * d3.y;
      p0 += __shfl_xor_sync(~0u, p0, 1); p0 += __shfl_xor_sync(~0u, p0, 2); p0 += __shfl_xor_sync(~0u, p0, 4);
      p1 += __shfl_xor_sync(~0u, p1, 1); p1 += __shfl_xor_sync(~0u, p1, 2); p1 += __shfl_xor_sync(~0u, p1, 4);
      p2 += __shfl_xor_sync(~0u, p2, 1); p2 += __shfl_xor_sync(~0u, p2, 2); p2 += __shfl_xor_sync(~0u, p2, 4);
      p3 += __shfl_xor_sync(~0u, p3, 1); p3 += __shfl_xor_sync(~0u, p3, 2); p3 += __shfl_xor_sync(~0u, p3, 4);
      if ((tid & 7) == 0) {
        float4 y = s.ys4[hC];
        float4 g; g.x = p0; g.y = p1; g.z = p2; g.w = p3;
        s.g04[hC] = g;
        float4 yp; yp.x = y.x + p0; yp.y = y.y + p1; yp.z = y.z + p2; yp.w = y.w + p3;
        s.yp4[hC] = yp;
      }
    }
    __syncthreads();

    // ================= phase D: c-net L0 at y' + drift final =============
    if (tid < 256) {
      float bi = fmaf(s.cW0t[0][jA], tcur, s.cb0[jA]);
      float2 r = dense2(&s.cW0t[1], jA, prDE, s.yp4, kH, bi);
      float2 h; h.x = lipswish(r.x); h.y = lipswish(r.y);
      *reinterpret_cast<float2*>(
          reinterpret_cast<float*>(&s.h0c4[jA]) + 2 * prDE) = h;
    } else if (tid < 320) {
      // drift final layer: one h for all 4 samples, streamed vW2t from L2
      float bias = s.vb2[hDr];
      u64 a01 = pack2(bias, bias), a23 = a01;
      u64 b01 = pack2(0.f, 0.f), b23 = b01;
#pragma unroll 8
      for (int k = 0; k < kW; k += 2) {
        float wa = __ldg(&g_vW2t[k * kH + hDr]);
        ulonglong2 xa = *reinterpret_cast<const ulonglong2*>(&s.h1v4[k]);
        u64 wa2 = pack2(wa, wa);
        a01 = fma2(wa2, xa.x, a01);
        a23 = fma2(wa2, xa.y, a23);
        float wb = __ldg(&g_vW2t[(k + 1) * kH + hDr]);
        ulonglong2 xb = *reinterpret_cast<const ulonglong2*>(&s.h1v4[k + 1]);
        u64 wb2 = pack2(wb, wb);
        b01 = fma2(wb2, xb.x, b01);
        b23 = fma2(wb2, xb.y, b23);
      }
      a01 = add2(a01, b01);
      a23 = add2(a23, b23);
      float r0, r1, r2, r3;
      unpack2(a01, r0, r1); unpack2(a23, r2, r3);
      float vs = s.vscl[hDr] * dt;
      float4 f; f.x = vs * tanh_fast(r0); f.y = vs * tanh_fast(r1);
      f.z = vs * tanh_fast(r2); f.w = vs * tanh_fast(r3);
      s.f04[hDr] = f;
    }
    __syncthreads();

    // ================= phase E: c-net L1 at y' ===========================
    if (tid < 256) {
      float2 r = dense2(s.cW1t, jA, prDE, s.h0c4, kW, s.cb1[jA]);
      float2 h; h.x = lipswish(r.x); h.y = lipswish(r.y);
      *reinterpret_cast<float2*>(
          reinterpret_cast<float*>(&s.h1c4[jA]) + 2 * prDE) = h;
    }
    __syncthreads();

    // ================= phase F: diffusion eval 2 + Heun update ===========
    {
      const float2 cb = *reinterpret_cast<const float2*>(&s.cb2[j0]);
      u64 A00 = pack2(cb.x, cb.x), A01 = A00;
      u64 A10 = pack2(cb.y, cb.y), A11 = A10;
#pragma unroll 16
      for (int k = 0; k < kW; ++k) {
        u64 w2 = wrowC[(size_t)k * (kCO / 2)];
        float wlo, whi; unpack2(w2, wlo, whi);
        u64 w00 = pack2(wlo, wlo);
        u64 w11 = pack2(whi, whi);
        ulonglong2 x = *reinterpret_cast<const ulonglong2*>(&s.h1c4[k]);
        A00 = fma2(w00, x.x, A00);
        A01 = fma2(w00, x.y, A01);
        A10 = fma2(w11, x.x, A10);
        A11 = fma2(w11, x.y, A11);
      }
      float csx = s.cscl[j0], csy = s.cscl[j0 + 1];
      int n0 = j0 & (kNoise - 1);
      float2 d0 = *reinterpret_cast<const float2*>(&s.dws[0][n0]);
      float2 d1 = *reinterpret_cast<const float2*>(&s.dws[1][n0]);
      float2 d2 = *reinterpret_cast<const float2*>(&s.dws[2][n0]);
      float2 d3 = *reinterpret_cast<const float2*>(&s.dws[3][n0]);
      float s0j0, s1j0, s2j0, s3j0, s0j1, s1j1, s2j1, s3j1;
      unpack2(A00, s0j0, s1j0); unpack2(A01, s2j0, s3j0);
      unpack2(A10, s0j1, s1j1); unpack2(A11, s2j1, s3j1);
      float p0 = tanh_fast(s0j0) * csx * d0.x + tanh_fast(s0j1) * csy * d0.y;
      float p1 = tanh_fast(s1j0) * csx * d1.x + tanh_fast(s1j1) * csy * d1.y;
      float p2 = tanh_fast(s2j0) * csx * d2.x + tanh_fast(s2j1) * csy * d2.y;
      float p3 = tanh_fast(s3j0) * csx * d3.x + tanh_fast(s3j1) * csy * d3.y;
      p0 += __shfl_xor_sync(~0u, p0, 1); p0 += __shfl_xor_sync(~0u, p0, 2); p0 += __shfl_xor_sync(~0u, p0, 4);
      p1 += __shfl_xor_sync(~0u, p1, 1); p1 += __shfl_xor_sync(~0u, p1, 2); p1 += __shfl_xor_sync(~0u, p1, 4);
      p2 += __shfl_xor_sync(~0u, p2, 1); p2 += __shfl_xor_sync(~0u, p2, 2); p2 += __shfl_xor_sync(~0u, p2, 4);
      p3 += __shfl_xor_sync(~0u, p3, 1); p3 += __shfl_xor_sync(~0u, p3, 2); p3 += __shfl_xor_sync(~0u, p3, 4);
      if ((tid & 7) == 0) {
        float4 y = s.ys4[hC];
        float4 f = s.f04[hC];
        float4 g = s.g04[hC];
        y.x += f.x + 0.5f * (g.x + p0);
        y.y += f.y + 0.5f * (g.y + p1);
        y.z += f.z + 0.5f * (g.z + p2);
        y.w += f.w + 0.5f * (g.w + p3);
        s.ys4[hC] = y;
      }
    }
    __syncthreads();
  }

  // final readout (index kSteps)
  if (tid < 32) {
    int b = tid >> 3, d = tid & 7;
    float acc = s.rob[d];
#pragma unroll
    for (int h = 0; h < kH; ++h)
      acc = fmaf(reinterpret_cast<const float*>(&s.ys4[h])[b], s.roWt[h][d], acc);
    out[((size_t)(bbase + b) * kT + kSteps) * kData + d] = acc;
  }
}

extern "C" void kernel_launch(void* const* d_in, const int* in_sizes, int n_in,
                              void* d_out, int out_size) {
  (void)in_sizes; (void)n_in; (void)out_size;
  const float* ts     = (const float*)d_in[0];
  const float* z0     = (const float*)d_in[1];
  const float* dW     = (const float*)d_in[2];
  const float* iW0    = (const float*)d_in[3];
  const float* ib0    = (const float*)d_in[4];
  const float* iW1    = (const float*)d_in[5];
  const float* ib1    = (const float*)d_in[6];
  const float* iW2    = (const float*)d_in[7];
  const float* ib2    = (const float*)d_in[8];
  const float* vW0    = (const float*)d_in[9];
  const float* vb0    = (const float*)d_in[10];
  const float* vW1    = (const float*)d_in[11];
  const float* vb1    = (const float*)d_in[12];
  const float* vW2    = (const float*)d_in[13];
  const float* vb2    = (const float*)d_in[14];
  const float* vscale = (const float*)d_in[15];
  const float* cW0    = (const float*)d_in[16];
  const float* cb0    = (const float*)d_in[17];
  const float* cW1    = (const float*)d_in[18];
  const float* cb1    = (const float*)d_in[19];
  const float* cW2    = (const float*)d_in[20];
  const float* cb2    = (const float*)d_in[21];
  const float* cscale = (const float*)d_in[22];
  const float* roW    = (const float*)d_in[23];
  const float* rob    = (const float*)d_in[24];

  cudaFuncSetAttribute(sde_kernel, cudaFuncAttributeMaxDynamicSharedMemorySize,
                       (int)sizeof(Smem));

  transpose_kernel<<<148, 256>>>(cW2, vW2);
  sde_kernel<<<NCTA, NTHR, sizeof(Smem)>>>(
      ts, z0, dW, iW0, ib0, iW1, ib1, iW2, ib2,
      vW0, vb0, vW1, vb1, vb2, vscale,
      cW0, cb0, cW1, cb1, cb2, cscale, roW, rob,
      (float*)d_out);
}

// round 17
// speedup vs baseline: 1.3135x; 1.0597x over previous
#include <cuda_runtime.h>
#include <math.h>

// ---------------------------------------------------------------------------
// NeuralSDE (Euler-Heun / Stratonovich) persistent kernel, round 16.
// Base = round-15 (16.53ms best). Change: the A->B and D->E full-block
// barriers are replaced by named barriers scoped to threads 0-255
// (bar.sync 1/2, 256). Readout+dW overlap the A+B span; the drift L2 stream
// overlaps D+E and only must complete by the full barrier before F.
// Arithmetic unchanged (bitwise identical results).
// ---------------------------------------------------------------------------

#define kH     64
#define kNoise 16
#define kData  8
#define kW     128
#define kB     512
#define kT     1025
#define kSteps 1024
#define BS     4
#define NCTA   128
#define NTHR   512
#define kCO    1024

using u64 = unsigned long long;

// Transposed big weights (k-major). 8B-aligned for packed loads.
__device__ u64   g_cW2t[kW * kCO / 2];   // float (k,j) at k*1024 + j
__device__ float g_vW2t[kW * kH];        // float (k,h) at k*64 + h

struct Smem {
  float vW0t[65][kW];
  float cW0t[65][kW];
  float vW1t[kW][kW];
  float cW1t[kW][kW];
  float vb0[kW], vb1[kW], cb0[kW], cb1[kW];
  float vb2[kH], vscl[kH];
  float cb2[kCO];
  float cscl[kCO];
  float roWt[kH][kData];
  float rob[kData];
  // activations: float4 over the 4 samples
  float4 ys4[kH];
  float4 g04[kH];
  float4 f04[kH];
  float4 yp4[kH];
  float4 h0v4[kW];
  float4 h0c4[kW];
  float4 h1v4[kW];
  float4 h1c4[kW];
  float  dws[BS][kNoise];
};

__global__ void transpose_kernel(const float* __restrict__ cW2,
                                 const float* __restrict__ vW2) {
  int idx = blockIdx.x * blockDim.x + threadIdx.x;
  int stride = gridDim.x * blockDim.x;
  float* ct = reinterpret_cast<float*>(g_cW2t);
  for (int i = idx; i < kW * kCO; i += stride) {
    int k = i >> 10, j = i & (kCO - 1);
    ct[i] = cW2[j * kW + k];            // cW2 is (1024, 128) row-major
  }
  for (int i = idx; i < kW * kH; i += stride) {
    int k = i >> 6, h = i & (kH - 1);
    g_vW2t[i] = vW2[h * kW + k];        // vW2 is (64, 128) row-major
  }
}

__device__ __forceinline__ u64 pack2(float lo, float hi) {
  u64 r; asm("mov.b64 %0,{%1,%2};" : "=l"(r) : "f"(lo), "f"(hi)); return r;
}
__device__ __forceinline__ void unpack2(u64 v, float& lo, float& hi) {
  asm("mov.b64 {%0,%1},%2;" : "=f"(lo), "=f"(hi) : "l"(v));
}
__device__ __forceinline__ u64 fma2(u64 a, u64 b, u64 c) {
  u64 d; asm("fma.rn.f32x2 %0,%1,%2,%3;" : "=l"(d) : "l"(a), "l"(b), "l"(c));
  return d;
}
__device__ __forceinline__ u64 add2(u64 a, u64 b) {
  u64 d; asm("add.rn.f32x2 %0,%1,%2;" : "=l"(d) : "l"(a), "l"(b));
  return d;
}

// Hardware tanh approximation (MUFU.TANH), max rel err ~2^-11.
__device__ __forceinline__ float tanh_fast(float x) {
  float y; asm("tanh.approx.f32 %0,%1;" : "=f"(y) : "f"(x));
  return y;
}

// lipswish(x) = 0.909 * x * sigmoid(x), sigmoid via 0.5 + 0.5*tanh(x/2).
__device__ __forceinline__ float lipswish(float x) {
  float t = tanh_fast(0.5f * x);
  return 0.909f * x * fmaf(0.5f, t, 0.5f);
}

// Named barrier for threads 0..255 (warps 0-7).
__device__ __forceinline__ void bar_sync_256(int id) {
  asm volatile("bar.sync %0, %1;" :: "r"(id), "r"(256) : "memory");
}

// One (net,j) output for all 4 samples (used in phases A/B; 256 threads).
__device__ __forceinline__ float4 dense4(const float (*Wt)[kW], int j,
                                         const float4* __restrict__ x4,
                                         int k0, int n, float bias0) {
  u64 a01 = pack2(bias0, bias0), a23 = a01;
  u64 b01 = pack2(0.f, 0.f), b23 = b01;
#pragma unroll 8
  for (int k = k0; k < k0 + n; k += 2) {
    float wa = Wt[k][j];
    ulonglong2 xa = *reinterpret_cast<const ulonglong2*>(&x4[k - k0]);
    u64 wa2 = pack2(wa, wa);
    a01 = fma2(wa2, xa.x, a01);
    a23 = fma2(wa2, xa.y, a23);
    float wb = Wt[k + 1][j];
    ulonglong2 xb = *reinterpret_cast<const ulonglong2*>(&x4[k + 1 - k0]);
    u64 wb2 = pack2(wb, wb);
    b01 = fma2(wb2, xb.x, b01);
    b23 = fma2(wb2, xb.y, b23);
  }
  a01 = add2(a01, b01);
  a23 = add2(a23, b23);
  float4 r;
  unpack2(a01, r.x, r.y);
  unpack2(a23, r.z, r.w);
  return r;
}

// One (net,j) output for 2 samples (pr half); used in phases D/E (256 thr).
__device__ __forceinline__ float2 dense2(const float (*Wt)[kW], int j, int pr,
                                         const float4* __restrict__ x4,
                                         int n, float bias0) {
  u64 a = pack2(bias0, bias0);
  u64 b = pack2(0.f, 0.f);
#pragma unroll 8
  for (int k = 0; k < n; k += 2) {
    float wa = Wt[k][j];
    u64 xa = *reinterpret_cast<const u64*>(
        reinterpret_cast<const float*>(&x4[k]) + 2 * pr);
    a = fma2(pack2(wa, wa), xa, a);
    float wb = Wt[k + 1][j];
    u64 xb = *reinterpret_cast<const u64*>(
        reinterpret_cast<const float*>(&x4[k + 1]) + 2 * pr);
    b = fma2(pack2(wb, wb), xb, b);
  }
  a = add2(a, b);
  float2 r;
  unpack2(a, r.x, r.y);
  return r;
}

__global__ __launch_bounds__(NTHR, 1) void sde_kernel(
    const float* __restrict__ ts, const float* __restrict__ z0,
    const float* __restrict__ dW,
    const float* __restrict__ iW0, const float* __restrict__ ib0,
    const float* __restrict__ iW1, const float* __restrict__ ib1,
    const float* __restrict__ iW2, const float* __restrict__ ib2,
    const float* __restrict__ vW0, const float* __restrict__ vb0,
    const float* __restrict__ vW1, const float* __restrict__ vb1,
    const float* __restrict__ vb2, const float* __restrict__ vscale,
    const float* __restrict__ cW0, const float* __restrict__ cb0,
    const float* __restrict__ cW1, const float* __restrict__ cb1,
    const float* __restrict__ cb2, const float* __restrict__ cscale,
    const float* __restrict__ roW, const float* __restrict__ rob,
    float* __restrict__ out) {
  extern __shared__ char smem_raw[];
  Smem& s = *reinterpret_cast<Smem*>(smem_raw);
  const int tid = threadIdx.x;
  const int bbase = blockIdx.x * BS;

  // ---- load small weights transposed into smem ----
  for (int i = tid; i < 65 * kW; i += NTHR) {
    int k = i >> 7, j = i & 127;
    s.vW0t[k][j] = vW0[j * 65 + k];
    s.cW0t[k][j] = cW0[j * 65 + k];
  }
  for (int i = tid; i < kW * kW; i += NTHR) {
    int k = i >> 7, j = i & 127;
    s.vW1t[k][j] = vW1[j * kW + k];
    s.cW1t[k][j] = cW1[j * kW + k];
  }
  for (int i = tid; i < kW; i += NTHR) {
    s.vb0[i] = vb0[i]; s.vb1[i] = vb1[i];
    s.cb0[i] = cb0[i]; s.cb1[i] = cb1[i];
  }
  for (int i = tid; i < kH; i += NTHR) { s.vb2[i] = vb2[i]; s.vscl[i] = vscale[i]; }
  for (int i = tid; i < kCO; i += NTHR) { s.cb2[i] = cb2[i]; s.cscl[i] = cscale[i]; }
  for (int i = tid; i < kH * kData; i += NTHR) {
    int h = i >> 3, d = i & 7;
    s.roWt[h][d] = roW[d * kH + h];
  }
  if (tid < kData) s.rob[tid] = rob[tid];
  __syncthreads();

  const float dt = __ldg(&ts[1]) - __ldg(&ts[0]);
  const float sqdt = sqrtf(dt);

  // ---- initial MLP: z0 (8) -> relu 128 -> relu 128 -> 64 ----
  if (tid < 256) {
    int j = tid & 127, pr = tid >> 7;  // samples 2pr, 2pr+1
    float a0 = __ldg(&ib0[j]), a1 = a0;
#pragma unroll
    for (int k = 0; k < 8; ++k) {
      float w = __ldg(&iW0[j * 8 + k]);
      a0 = fmaf(w, __ldg(&z0[(bbase + 2 * pr) * 8 + k]), a0);
      a1 = fmaf(w, __ldg(&z0[(bbase + 2 * pr + 1) * 8 + k]), a1);
    }
    float* d0 = reinterpret_cast<float*>(&s.h0v4[j]) + 2 * pr;
    d0[0] = fmaxf(a0, 0.f); d0[1] = fmaxf(a1, 0.f);
  }
  __syncthreads();
  if (tid < 256) {
    int j = tid & 127, pr = tid >> 7;
    float a0 = __ldg(&ib1[j]), a1 = a0;
#pragma unroll 4
    for (int k = 0; k < kW; ++k) {
      float w = __ldg(&iW1[j * kW + k]);
      const float* x = reinterpret_cast<const float*>(&s.h0v4[k]) + 2 * pr;
      a0 = fmaf(w, x[0], a0);
      a1 = fmaf(w, x[1], a1);
    }
    float* d0 = reinterpret_cast<float*>(&s.h0c4[j]) + 2 * pr;  // temp
    d0[0] = fmaxf(a0, 0.f); d0[1] = fmaxf(a1, 0.f);
  }
  __syncthreads();
  if (tid < 256) {
    int b = tid >> 6, h = tid & 63;
    float acc = __ldg(&ib2[h]);
#pragma unroll 4
    for (int k = 0; k < kW; ++k)
      acc = fmaf(reinterpret_cast<const float*>(&s.h0c4[k])[b],
                 __ldg(&iW2[h * kW + k]), acc);
    reinterpret_cast<float*>(&s.ys4[h])[b] = acc;
  }
  __syncthreads();

  // precomputed per-thread constants
  const int jA = tid & 127;             // phases A/B: (net, j), 4 samples
  const int netA = tid >> 7;            // valid for tid < 256
  const int prDE = tid >> 7;            // phases D/E sample pair (tid < 256)
  const int j0 = tid << 1;              // diffusion col pair (phases C/F)
  const int hC = tid >> 3;              // diffusion h
  const u64* wrowC = g_cW2t + tid;      // row k at + k*512 (u64 units)
  const int hDr = tid - 256;            // drift h (tid in [256,320))

  for (int st = 0; st < kSteps; ++st) {
    const float tcur = __ldg(&ts[st]);

    // ====== phases A+B (threads 0-255, named barrier) || extras ==========
    if (tid < 256) {
      // phase A: dense L0 of both nets
      {
        const float (*W0)[kW] = netA ? s.cW0t : s.vW0t;
        const float* bb = netA ? s.cb0 : s.vb0;
        float bi = fmaf(W0[0][jA], tcur, bb[jA]);
        float4 r = dense4(&W0[1], jA, s.ys4, 0, kH, bi);
        float4 h; h.x = lipswish(r.x); h.y = lipswish(r.y);
        h.z = lipswish(r.z); h.w = lipswish(r.w);
        (netA ? s.h0c4 : s.h0v4)[jA] = h;
      }
      bar_sync_256(1);
      // phase B: dense L1 of both nets
      {
        const float (*W1)[kW] = netA ? s.cW1t : s.vW1t;
        const float* bb = netA ? s.cb1 : s.vb1;
        const float4* src = netA ? s.h0c4 : s.h0v4;
        float4 r = dense4(W1, jA, src, 0, kW, bb[jA]);
        float4 h; h.x = lipswish(r.x); h.y = lipswish(r.y);
        h.z = lipswish(r.z); h.w = lipswish(r.w);
        (netA ? s.h1c4 : s.h1v4)[jA] = h;
      }
    } else if (tid >= 448) {
      int i = tid - 448;                 // 64 tasks: dW load
      int b = i >> 4, n = i & 15;
      s.dws[b][n] = __ldg(&dW[((size_t)st * kB + bbase + b) * kNoise + n]) * sqdt;
    } else if (tid >= 416) {
      int i = tid - 416;                 // 32 tasks: readout of y_st
      int b = i >> 3, d = i & 7;
      float acc = s.rob[d];
#pragma unroll
      for (int h = 0; h < kH; ++h)
        acc = fmaf(reinterpret_cast<const float*>(&s.ys4[h])[b], s.roWt[h][d], acc);
      out[((size_t)(bbase + b) * kT + st) * kData + d] = acc;
    }
    __syncthreads();

    // ================= phase C: diffusion eval 1 (all threads) ===========
    {
      const float2 cb = *reinterpret_cast<const float2*>(&s.cb2[j0]);
      u64 A00 = pack2(cb.x, cb.x), A01 = A00;   // col j0: samples(0,1),(2,3)
      u64 A10 = pack2(cb.y, cb.y), A11 = A10;   // col j0+1
#pragma unroll 16
      for (int k = 0; k < kW; ++k) {
        u64 w2 = wrowC[(size_t)k * (kCO / 2)];
        float wlo, whi; unpack2(w2, wlo, whi);
        u64 w00 = pack2(wlo, wlo);
        u64 w11 = pack2(whi, whi);
        ulonglong2 x = *reinterpret_cast<const ulonglong2*>(&s.h1c4[k]);
        A00 = fma2(w00, x.x, A00);
        A01 = fma2(w00, x.y, A01);
        A10 = fma2(w11, x.x, A10);
        A11 = fma2(w11, x.y, A11);
      }
      float csx = s.cscl[j0], csy = s.cscl[j0 + 1];
      int n0 = j0 & (kNoise - 1);
      float2 d0 = *reinterpret_cast<const float2*>(&s.dws[0][n0]);
      float2 d1 = *reinterpret_cast<const float2*>(&s.dws[1][n0]);
      float2 d2 = *reinterpret_cast<const float2*>(&s.dws[2][n0]);
      float2 d3 = *reinterpret_cast<const float2*>(&s.dws[3][n0]);
      float s0j0, s1j0, s2j0, s3j0, s0j1, s1j1, s2j1, s3j1;
      unpack2(A00, s0j0, s1j0); unpack2(A01, s2j0, s3j0);
      unpack2(A10, s0j1, s1j1); unpack2(A11, s2j1, s3j1);
      float p0 = tanh_fast(s0j0) * csx * d0.x + tanh_fast(s0j1) * csy * d0.y;
      float p1 = tanh_fast(s1j0) * csx * d1.x + tanh_fast(s1j1) * csy * d1.y;
      float p2 = tanh_fast(s2j0) * csx * d2.x + tanh_fast(s2j1) * csy * d2.y;
      float p3 = tanh_fast(s3j0) * csx * d3.x + tanh_fast(s3j1) * csy * d3.y;
      p0 += __shfl_xor_sync(~0u, p0, 1); p0 += __shfl_xor_sync(~0u, p0, 2); p0 += __shfl_xor_sync(~0u, p0, 4);
      p1 += __shfl_xor_sync(~0u, p1, 1); p1 += __shfl_xor_sync(~0u, p1, 2); p1 += __shfl_xor_sync(~0u, p1, 4);
      p2 += __shfl_xor_sync(~0u, p2, 1); p2 += __shfl_xor_sync(~0u, p2, 2); p2 += __shfl_xor_sync(~0u, p2, 4);
      p3 += __shfl_xor_sync(~0u, p3, 1); p3 += __shfl_xor_sync(~0u, p3, 2); p3 += __shfl_xor_sync(~0u, p3, 4);
      if ((tid & 7) == 0) {
        float4 y = s.ys4[hC];
        float4 g; g.x = p0; g.y = p1; g.z = p2; g.w = p3;
        s.g04[hC] = g;
        float4 yp; yp.x = y.x + p0; yp.y = y.y + p1; yp.z = y.z + p2; yp.w = y.w + p3;
        s.yp4[hC] = yp;
      }
    }
    __syncthreads();

    // ====== phases D+E (threads 0-255, named barrier) || drift ===========
    if (tid < 256) {
      // phase D: c-net L0 at y'
      {
        float bi = fmaf(s.cW0t[0][jA], tcur, s.cb0[jA]);
        float2 r = dense2(&s.cW0t[1], jA, prDE, s.yp4, kH, bi);
        float2 h; h.x = lipswish(r.x); h.y = lipswish(r.y);
        *reinterpret_cast<float2*>(
            reinterpret_cast<float*>(&s.h0c4[jA]) + 2 * prDE) = h;
      }
      bar_sync_256(2);
      // phase E: c-net L1 at y'
      {
        float2 r = dense2(s.cW1t, jA, prDE, s.h0c4, kW, s.cb1[jA]);
        float2 h; h.x = lipswish(r.x); h.y = lipswish(r.y);
        *reinterpret_cast<float2*>(
            reinterpret_cast<float*>(&s.h1c4[jA]) + 2 * prDE) = h;
      }
    } else if (tid < 320) {
      // drift final layer: one h for all 4 samples, streamed vW2t from L2
      float bias = s.vb2[hDr];
      u64 a01 = pack2(bias, bias), a23 = a01;
      u64 b01 = pack2(0.f, 0.f), b23 = b01;
#pragma unroll 8
      for (int k = 0; k < kW; k += 2) {
        float wa = __ldg(&g_vW2t[k * kH + hDr]);
        ulonglong2 xa = *reinterpret_cast<const ulonglong2*>(&s.h1v4[k]);
        u64 wa2 = pack2(wa, wa);
        a01 = fma2(wa2, xa.x, a01);
        a23 = fma2(wa2, xa.y, a23);
        float wb = __ldg(&g_vW2t[(k + 1) * kH + hDr]);
        ulonglong2 xb = *reinterpret_cast<const ulonglong2*>(&s.h1v4[k + 1]);
        u64 wb2 = pack2(wb, wb);
        b01 = fma2(wb2, xb.x, b01);
        b23 = fma2(wb2, xb.y, b23);
      }
      a01 = add2(a01, b01);
      a23 = add2(a23, b23);
      float r0, r1, r2, r3;
      unpack2(a01, r0, r1); unpack2(a23, r2, r3);
      float vs = s.vscl[hDr] * dt;
      float4 f; f.x = vs * tanh_fast(r0); f.y = vs * tanh_fast(r1);
      f.z = vs * tanh_fast(r2); f.w = vs * tanh_fast(r3);
      s.f04[hDr] = f;
    }
    __syncthreads();

    // ================= phase F: diffusion eval 2 + Heun update ===========
    {
      const float2 cb = *reinterpret_cast<const float2*>(&s.cb2[j0]);
      u64 A00 = pack2(cb.x, cb.x), A01 = A00;
      u64 A10 = pack2(cb.y, cb.y), A11 = A10;
#pragma unroll 16
      for (int k = 0; k < kW; ++k) {
        u64 w2 = wrowC[(size_t)k * (kCO / 2)];
        float wlo, whi; unpack2(w2, wlo, whi);
        u64 w00 = pack2(wlo, wlo);
        u64 w11 = pack2(whi, whi);
        ulonglong2 x = *reinterpret_cast<const ulonglong2*>(&s.h1c4[k]);
        A00 = fma2(w00, x.x, A00);
        A01 = fma2(w00, x.y, A01);
        A10 = fma2(w11, x.x, A10);
        A11 = fma2(w11, x.y, A11);
      }
      float csx = s.cscl[j0], csy = s.cscl[j0 + 1];
      int n0 = j0 & (kNoise - 1);
      float2 d0 = *reinterpret_cast<const float2*>(&s.dws[0][n0]);
      float2 d1 = *reinterpret_cast<const float2*>(&s.dws[1][n0]);
      float2 d2 = *reinterpret_cast<const float2*>(&s.dws[2][n0]);
      float2 d3 = *reinterpret_cast<const float2*>(&s.dws[3][n0]);
      float s0j0, s1j0, s2j0, s3j0, s0j1, s1j1, s2j1, s3j1;
      unpack2(A00, s0j0, s1j0); unpack2(A01, s2j0, s3j0);
      unpack2(A10, s0j1, s1j1); unpack2(A11, s2j1, s3j1);
      float p0 = tanh_fast(s0j0) * csx * d0.x + tanh_fast(s0j1) * csy * d0.y;
      float p1 = tanh_fast(s1j0) * csx * d1.x + tanh_fast(s1j1) * csy * d1.y;
      float p2 = tanh_fast(s2j0) * csx * d2.x + tanh_fast(s2j1) * csy * d2.y;
      float p3 = tanh_fast(s3j0) * csx * d3.x + tanh_fast(s3j1) * csy * d3.y;
      p0 += __shfl_xor_sync(~0u, p0, 1); p0 += __shfl_xor_sync(~0u, p0, 2); p0 += __shfl_xor_sync(~0u, p0, 4);
      p1 += __shfl_xor_sync(~0u, p1, 1); p1 += __shfl_xor_sync(~0u, p1, 2); p1 += __shfl_xor_sync(~0u, p1, 4);
      p2 += __shfl_xor_sync(~0u, p2, 1); p2 += __shfl_xor_sync(~0u, p2, 2); p2 += __shfl_xor_sync(~0u, p2, 4);
      p3 += __shfl_xor_sync(~0u, p3, 1); p3 += __shfl_xor_sync(~0u, p3, 2); p3 += __shfl_xor_sync(~0u, p3, 4);
      if ((tid & 7) == 0) {
        float4 y = s.ys4[hC];
        float4 f = s.f04[hC];
        float4 g = s.g04[hC];
        y.x += f.x + 0.5f * (g.x + p0);
        y.y += f.y + 0.5f * (g.y + p1);
        y.z += f.z + 0.5f * (g.z + p2);
        y.w += f.w + 0.5f * (g.w + p3);
        s.ys4[hC] = y;
      }
    }
    __syncthreads();
  }

  // final readout (index kSteps)
  if (tid < 32) {
    int b = tid >> 3, d = tid & 7;
    float acc = s.rob[d];
#pragma unroll
    for (int h = 0; h < kH; ++h)
      acc = fmaf(reinterpret_cast<const float*>(&s.ys4[h])[b], s.roWt[h][d], acc);
    out[((size_t)(bbase + b) * kT + kSteps) * kData + d] = acc;
  }
}

extern "C" void kernel_launch(void* const* d_in, const int* in_sizes, int n_in,
                              void* d_out, int out_size) {
  (void)in_sizes; (void)n_in; (void)out_size;
  const float* ts     = (const float*)d_in[0];
  const float* z0     = (const float*)d_in[1];
  const float* dW     = (const float*)d_in[2];
  const float* iW0    = (const float*)d_in[3];
  const float* ib0    = (const float*)d_in[4];
  const float* iW1    = (const float*)d_in[5];
  const float* ib1    = (const float*)d_in[6];
  const float* iW2    = (const float*)d_in[7];
  const float* ib2    = (const float*)d_in[8];
  const float* vW0    = (const float*)d_in[9];
  const float* vb0    = (const float*)d_in[10];
  const float* vW1    = (const float*)d_in[11];
  const float* vb1    = (const float*)d_in[12];
  const float* vW2    = (const float*)d_in[13];
  const float* vb2    = (const float*)d_in[14];
  const float* vscale = (const float*)d_in[15];
  const float* cW0    = (const float*)d_in[16];
  const float* cb0    = (const float*)d_in[17];
  const float* cW1    = (const float*)d_in[18];
  const float* cb1    = (const float*)d_in[19];
  const float* cW2    = (const float*)d_in[20];
  const float* cb2    = (const float*)d_in[21];
  const float* cscale = (const float*)d_in[22];
  const float* roW    = (const float*)d_in[23];
  const float* rob    = (const float*)d_in[24];

  cudaFuncSetAttribute(sde_kernel, cudaFuncAttributeMaxDynamicSharedMemorySize,
                       (int)sizeof(Smem));

  transpose_kernel<<<148, 256>>>(cW2, vW2);
  sde_kernel<<<NCTA, NTHR, sizeof(Smem)>>>(
      ts, z0, dW, iW0, ib0, iW1, ib1, iW2, ib2,
      vW0, vb0, vW1, vb1, vb2, vscale,
      cW0, cb0, cW1, cb1, cb2, cscale, roW, rob,
      (float*)d_out);
}